// round 8
// baseline (speedup 1.0000x reference)
#include <cuda_runtime.h>
#include <cstdint>

#define NB 8
#define NL 2048
#define ND 64
#define SCAP 256
#define STHRESH 35.0f
#define NITER 100

// ---------------- static device scratch (no runtime allocation) ----------------
static __device__ float    d_P[(size_t)NB * NL * NL];   // dense scores (134 MB), reused for self & cross
static __device__ unsigned d_mA[NB * NL];               // encoded row max (self)
static __device__ unsigned d_mC[NB * NL];               // encoded row max (cross)
static __device__ float    d_rbA[NB * NL];              // -0.5*||pos||^2
static __device__ float    d_cbA[NB * NL];              // lw - 0.5*||pos||^2
static __device__ float    d_rbC[NB * NL];              // -0.5*||tpos||^2
static __device__ float    d_cbC[NB * NL];              // lw + f - 0.5*||pos||^2 (after iterate)
static __device__ int      d_scnt[NB * NL];             // nnz per row
static __device__ int      d_scol[(size_t)NB * NL * SCAP];
static __device__ float    d_sval[(size_t)NB * NL * SCAP];
static __device__ float    d_gw[NB * NL];               // g * exp(tlw) partials

// monotone float<->uint encoding for atomicMax on floats (any sign)
__device__ __forceinline__ unsigned fenc(float f) {
    unsigned u = __float_as_uint(f);
    return (u & 0x80000000u) ? ~u : (u | 0x80000000u);
}
__device__ __forceinline__ float fdec(unsigned e) {
    return __uint_as_float((e & 0x80000000u) ? (e ^ 0x80000000u) : ~e);
}

// ---------------- prep: norms, biases, max init ----------------
__global__ void prep_kernel(const float* __restrict__ pos,
                            const float* __restrict__ lw,
                            const float* __restrict__ tpos)
{
    int i = blockIdx.x * blockDim.x + threadIdx.x;
    if (i >= NB * NL) return;
    const float* p = pos  + (size_t)i * ND;
    const float* t = tpos + (size_t)i * ND;
    float sp = 0.f, st = 0.f;
#pragma unroll
    for (int d = 0; d < ND; d++) { sp += p[d] * p[d]; st += t[d] * t[d]; }
    d_rbA[i] = -0.5f * sp;
    d_cbA[i] = lw[i] - 0.5f * sp;
    d_rbC[i] = -0.5f * st;
    d_mA[i] = 0u;   // below every valid encoding
    d_mC[i] = 0u;
}

// ---------------- dense score pass: out = X.Y^T + rowbias + colbias, with row max ----------------
// PHASE 0: self (X=pos, Y=pos, rb=d_rbA, cb=d_cbA, max->d_mA)
// PHASE 1: cross (X=tpos, Y=pos, rb=d_rbC, cb=d_cbC, max->d_mC)
template <int PHASE>
__global__ __launch_bounds__(256) void score_kernel(const float* __restrict__ X,
                                                    const float* __restrict__ Y)
{
    __shared__ float Xs[64][65];
    __shared__ float Ys[64][65];
    __shared__ unsigned rowm[64];
    const int b  = blockIdx.z;
    const int rt = blockIdx.y * 64;
    const int ct = blockIdx.x * 64;
    const int tid = threadIdx.x;

    const float* Xb = X + ((size_t)b * NL + rt) * ND;
    const float* Yb = Y + ((size_t)b * NL + ct) * ND;
    for (int i = tid; i < 64 * 64; i += 256) {
        int r = i >> 6, d = i & 63;
        Xs[r][d] = Xb[(size_t)r * ND + d];
        Ys[r][d] = Yb[(size_t)r * ND + d];
    }
    if (tid < 64) rowm[tid] = 0u;
    __syncthreads();

    const int tx = tid & 15, ty = tid >> 4;
    float acc[4][4];
#pragma unroll
    for (int i = 0; i < 4; i++)
#pragma unroll
        for (int j = 0; j < 4; j++) acc[i][j] = 0.f;

#pragma unroll
    for (int d = 0; d < 64; d++) {
        float xa[4], yv[4];
#pragma unroll
        for (int i = 0; i < 4; i++) xa[i] = Xs[ty * 4 + i][d];
#pragma unroll
        for (int j = 0; j < 4; j++) yv[j] = Ys[tx * 4 + j][d];
#pragma unroll
        for (int i = 0; i < 4; i++)
#pragma unroll
            for (int j = 0; j < 4; j++) acc[i][j] = fmaf(xa[i], yv[j], acc[i][j]);
    }

    const float* rb  = (PHASE == 0) ? d_rbA : d_rbC;
    const float* cb  = (PHASE == 0) ? d_cbA : d_cbC;
    unsigned*    men = (PHASE == 0) ? d_mA  : d_mC;

    float cbv[4];
#pragma unroll
    for (int j = 0; j < 4; j++) cbv[j] = cb[b * NL + ct + tx * 4 + j];

#pragma unroll
    for (int i = 0; i < 4; i++) {
        int r = rt + ty * 4 + i;
        float rbv = rb[b * NL + r];
        float4 v;
        v.x = acc[i][0] + rbv + cbv[0];
        v.y = acc[i][1] + rbv + cbv[1];
        v.z = acc[i][2] + rbv + cbv[2];
        v.w = acc[i][3] + rbv + cbv[3];
        *reinterpret_cast<float4*>(&d_P[((size_t)b * NL + r) * NL + ct + tx * 4]) = v;
        float mx = fmaxf(fmaxf(v.x, v.y), fmaxf(v.z, v.w));
        atomicMax(&rowm[ty * 4 + i], fenc(mx));
    }
    __syncthreads();
    if (tid < 64) atomicMax(&men[b * NL + rt + tid], rowm[tid]);
}

// ---------------- sparse build: warp per row, deterministic ordered compaction ----------------
__global__ __launch_bounds__(256) void sparse_build_kernel()
{
    int gtid = blockIdx.x * blockDim.x + threadIdx.x;
    int w    = gtid >> 5;       // row index (b*NL + l)
    int lane = gtid & 31;
    if (w >= NB * NL) return;
    const float* Pr = d_P + (size_t)w * NL;
    float m = fdec(d_mA[w]);
    float thr = m - STHRESH;
    int base = 0;
    size_t sb = (size_t)w * SCAP;
    for (int k0 = 0; k0 < NL; k0 += 32) {
        float p = Pr[k0 + lane];
        bool keep = (p > thr);
        unsigned mask = __ballot_sync(0xFFFFFFFFu, keep);
        if (keep) {
            int pos = base + __popc(mask & ((1u << lane) - 1u));
            if (pos < SCAP) {
                d_scol[sb + pos] = k0 + lane;
                d_sval[sb + pos] = __expf(p - m);
            }
        }
        base += __popc(mask);
    }
    if (lane == 0) d_scnt[w] = (base < SCAP) ? base : SCAP;
}

// ---------------- 100 iterations in one launch: one block per batch ----------------
__global__ __launch_bounds__(1024) void iterate_kernel(const float* __restrict__ lw)
{
    const int b   = blockIdx.x;
    const int tid = threadIdx.x;        // 1024 threads, 2 rows each
    __shared__ float fs[NL];
    __shared__ float us[NL];
    __shared__ float ms[NL];
    __shared__ int   cns[NL];

    for (int r = tid; r < NL; r += 1024) {
        fs[r]  = 0.f;
        ms[r]  = fdec(d_mA[b * NL + r]);
        cns[r] = d_scnt[b * NL + r];
    }
    __syncthreads();

    const int r0 = tid, r1 = tid + 1024;
    const size_t sb0 = ((size_t)b * NL + r0) * SCAP;
    const size_t sb1 = ((size_t)b * NL + r1) * SCAP;
    const int n0 = cns[r0], n1 = cns[r1];

    for (int it = 0; it < NITER; it++) {
        us[r0] = __expf(fs[r0]);
        us[r1] = __expf(fs[r1]);
        __syncthreads();
        float s0 = 0.f;
        for (int j = 0; j < n0; j++) s0 += d_sval[sb0 + j] * us[d_scol[sb0 + j]];
        float s1 = 0.f;
        for (int j = 0; j < n1; j++) s1 += d_sval[sb1 + j] * us[d_scol[sb1 + j]];
        float fn0 = 0.5f * (fs[r0] - ms[r0] - __logf(s0));
        float fn1 = 0.5f * (fs[r1] - ms[r1] - __logf(s1));
        __syncthreads();   // all u-reads done before anyone overwrites f/u
        fs[r0] = fn0;
        fs[r1] = fn1;
    }
    __syncthreads();
    // column bias for the cross pass: lw_l + f_l - 0.5*||pos_l||^2
    for (int r = tid; r < NL; r += 1024)
        d_cbC[b * NL + r] = lw[b * NL + r] + fs[r] + d_rbA[b * NL + r];
}

// ---------------- cross LSE: block per target row (max precomputed by score<1>) ----------------
__global__ __launch_bounds__(256) void lse_cross_kernel(const float* __restrict__ tlw)
{
    const int row = blockIdx.x;              // b*NL + t
    const float* Sr = d_P + (size_t)row * NL;
    float m = fdec(d_mC[row]);
    float s = 0.f;
    for (int k = threadIdx.x; k < NL; k += 256) s += __expf(Sr[k] - m);
    __shared__ float red[256];
    red[threadIdx.x] = s;
    __syncthreads();
    for (int off = 128; off > 0; off >>= 1) {
        if (threadIdx.x < off) red[threadIdx.x] += red[threadIdx.x + off];
        __syncthreads();
    }
    if (threadIdx.x == 0) {
        float g = -(m + __logf(red[0]));
        d_gw[row] = g * __expf(tlw[row]);
    }
}

// ---------------- deterministic final reduction ----------------
__global__ __launch_bounds__(256) void reduce_kernel(float* __restrict__ out)
{
    const int b = blockIdx.x;
    float s = 0.f;
    for (int k = threadIdx.x; k < NL; k += 256) s += d_gw[b * NL + k];
    __shared__ float red[256];
    red[threadIdx.x] = s;
    __syncthreads();
    for (int off = 128; off > 0; off >>= 1) {
        if (threadIdx.x < off) red[threadIdx.x] += red[threadIdx.x + off];
        __syncthreads();
    }
    if (threadIdx.x == 0) out[b] = red[0];
}

// ---------------- launch ----------------
extern "C" void kernel_launch(void* const* d_in, const int* in_sizes, int n_in,
                              void* d_out, int out_size)
{
    const float* pos  = (const float*)d_in[0];   // (8, 2048, 64)
    const float* lw   = (const float*)d_in[1];   // (8, 2048)
    const float* tpos = (const float*)d_in[2];   // (8, 2048, 64)
    const float* tlw  = (const float*)d_in[3];   // (8, 2048)
    float* out = (float*)d_out;                  // (8,)

    prep_kernel<<<(NB * NL + 255) / 256, 256>>>(pos, lw, tpos);

    dim3 g(NL / 64, NL / 64, NB);
    score_kernel<0><<<g, 256>>>(pos, pos);

    sparse_build_kernel<<<(NB * NL * 32) / 256, 256>>>();

    iterate_kernel<<<NB, 1024>>>(lw);

    score_kernel<1><<<g, 256>>>(tpos, pos);

    lse_cross_kernel<<<NB * NL, 256>>>(tlw);

    reduce_kernel<<<NB, 256>>>(out);
}

// round 9
// speedup vs baseline: 1.1501x; 1.1501x over previous
#include <cuda_runtime.h>
#include <cstdint>

#define NB 8
#define NL 2048
#define ND 64
#define SCAP 256
#define STHRESH 35.0f
#define NITER 100

// ---------------- static device scratch (no runtime allocation) ----------------
static __device__ float    d_P[(size_t)NB * NL * NL];   // dense scores (134 MB), reused self & cross
static __device__ unsigned d_mA[NB * NL];               // encoded row max (self)
static __device__ unsigned d_mC[NB * NL];               // encoded row max (cross)
static __device__ float    d_rbA[NB * NL];              // -0.5*||pos||^2
static __device__ float    d_cbA[NB * NL];              // lw - 0.5*||pos||^2
static __device__ float    d_rbC[NB * NL];              // -0.5*||tpos||^2
static __device__ float    d_cbC[NB * NL];              // lw + f - 0.5*||pos||^2 (after iterate)
static __device__ int      d_scnt[NB * NL];             // padded nnz per row (multiple of 4)
static __device__ float2   d_sv2[(size_t)NB * NL * SCAP]; // packed (col_bits, exp(p-m))
static __device__ float    d_gw[NB * NL];               // g * exp(tlw) partials

// monotone float<->uint encoding for atomicMax on floats (any sign)
__device__ __forceinline__ unsigned fenc(float f) {
    unsigned u = __float_as_uint(f);
    return (u & 0x80000000u) ? ~u : (u | 0x80000000u);
}
__device__ __forceinline__ float fdec(unsigned e) {
    return __uint_as_float((e & 0x80000000u) ? (e ^ 0x80000000u) : ~e);
}

// packed f32x2 helpers (sm_100+)
__device__ __forceinline__ unsigned long long pk2(float x, float y) {
    unsigned long long r;
    asm("mov.b64 %0, {%1, %2};" : "=l"(r) : "f"(x), "f"(y));
    return r;
}
__device__ __forceinline__ unsigned long long dup2(float x) {
    unsigned long long r;
    asm("mov.b64 %0, {%1, %1};" : "=l"(r) : "f"(x));
    return r;
}
__device__ __forceinline__ float2 upk(unsigned long long v) {
    float2 r;
    asm("mov.b64 {%0, %1}, %2;" : "=f"(r.x), "=f"(r.y) : "l"(v));
    return r;
}
__device__ __forceinline__ void ffma2(unsigned long long& d,
                                      unsigned long long a, unsigned long long b) {
    asm("fma.rn.f32x2 %0, %1, %2, %0;" : "+l"(d) : "l"(a), "l"(b));
}

// ---------------- prep: norms, biases, max init ----------------
__global__ void prep_kernel(const float* __restrict__ pos,
                            const float* __restrict__ lw,
                            const float* __restrict__ tpos)
{
    int i = blockIdx.x * blockDim.x + threadIdx.x;
    if (i >= NB * NL) return;
    const float* p = pos  + (size_t)i * ND;
    const float* t = tpos + (size_t)i * ND;
    float sp = 0.f, st = 0.f;
#pragma unroll
    for (int d = 0; d < ND; d++) { sp += p[d] * p[d]; st += t[d] * t[d]; }
    d_rbA[i] = -0.5f * sp;
    d_cbA[i] = lw[i] - 0.5f * sp;
    d_rbC[i] = -0.5f * st;
    d_mA[i] = 0u;   // below every valid encoding
    d_mC[i] = 0u;
}

// ---------------- dense score pass: P = X.Y^T + rowbias + colbias, with row max ----------------
// 128x128 tile per block, 8x8 per thread, packed f32x2 FFMA, K staged in 2 halves of 32.
// PHASE 0: self (X=pos, Y=pos, rb=d_rbA, cb=d_cbA, max->d_mA)
// PHASE 1: cross (X=tpos, Y=pos, rb=d_rbC, cb=d_cbC, max->d_mC)
#define SPAD 132   // 128 + 4 floats: keeps float4 groups 16B-aligned, limits conflicts
template <int PHASE>
__global__ __launch_bounds__(256, 2) void score_kernel(const float* __restrict__ X,
                                                       const float* __restrict__ Y)
{
    __shared__ float XsT[32][SPAD];   // transposed: [d][row]
    __shared__ float YsT[32][SPAD];   // transposed: [d][col]
    __shared__ unsigned rowm[128];

    const int b  = blockIdx.z;
    const int rt = blockIdx.y * 128;
    const int ct = blockIdx.x * 128;
    const int tid = threadIdx.x;
    const int tx = tid & 15;          // col group
    const int ty = tid >> 4;          // row group

    const float* Xb = X + ((size_t)b * NL + rt) * ND;
    const float* Yb = Y + ((size_t)b * NL + ct) * ND;

    if (tid < 128) rowm[tid] = 0u;

    unsigned long long acc2[8][4];
#pragma unroll
    for (int i = 0; i < 8; i++)
#pragma unroll
        for (int jp = 0; jp < 4; jp++) acc2[i][jp] = 0ull;

#pragma unroll
    for (int ks = 0; ks < 64; ks += 32) {
        __syncthreads();
        // load 128 rows x 32 d, transposed into smem
        for (int i = tid; i < 128 * 8; i += 256) {
            int r  = i >> 3;
            int dv = (i & 7) * 4;
            float4 vx = *reinterpret_cast<const float4*>(&Xb[(size_t)r * ND + ks + dv]);
            XsT[dv + 0][r] = vx.x; XsT[dv + 1][r] = vx.y;
            XsT[dv + 2][r] = vx.z; XsT[dv + 3][r] = vx.w;
            float4 vy = *reinterpret_cast<const float4*>(&Yb[(size_t)r * ND + ks + dv]);
            YsT[dv + 0][r] = vy.x; YsT[dv + 1][r] = vy.y;
            YsT[dv + 2][r] = vy.z; YsT[dv + 3][r] = vy.w;
        }
        __syncthreads();

#pragma unroll 8
        for (int d = 0; d < 32; d++) {
            float4 x0 = *reinterpret_cast<const float4*>(&XsT[d][ty * 8]);
            float4 x1 = *reinterpret_cast<const float4*>(&XsT[d][ty * 8 + 4]);
            float4 y0 = *reinterpret_cast<const float4*>(&YsT[d][tx * 8]);
            float4 y1 = *reinterpret_cast<const float4*>(&YsT[d][tx * 8 + 4]);
            unsigned long long b2[4];
            b2[0] = pk2(y0.x, y0.y); b2[1] = pk2(y0.z, y0.w);
            b2[2] = pk2(y1.x, y1.y); b2[3] = pk2(y1.z, y1.w);
            unsigned long long a2[8];
            a2[0] = dup2(x0.x); a2[1] = dup2(x0.y); a2[2] = dup2(x0.z); a2[3] = dup2(x0.w);
            a2[4] = dup2(x1.x); a2[5] = dup2(x1.y); a2[6] = dup2(x1.z); a2[7] = dup2(x1.w);
#pragma unroll
            for (int i = 0; i < 8; i++)
#pragma unroll
                for (int jp = 0; jp < 4; jp++) ffma2(acc2[i][jp], a2[i], b2[jp]);
        }
    }

    const float* rb  = (PHASE == 0) ? d_rbA : d_rbC;
    const float* cb  = (PHASE == 0) ? d_cbA : d_cbC;
    unsigned*    men = (PHASE == 0) ? d_mA  : d_mC;

    float cbv[8];
#pragma unroll
    for (int j = 0; j < 8; j++) cbv[j] = cb[b * NL + ct + tx * 8 + j];

#pragma unroll
    for (int i = 0; i < 8; i++) {
        int r = rt + ty * 8 + i;
        float rbv = rb[b * NL + r];
        float v[8];
#pragma unroll
        for (int jp = 0; jp < 4; jp++) {
            float2 p = upk(acc2[i][jp]);
            v[2 * jp]     = p.x + rbv + cbv[2 * jp];
            v[2 * jp + 1] = p.y + rbv + cbv[2 * jp + 1];
        }
        float4 s0 = make_float4(v[0], v[1], v[2], v[3]);
        float4 s1 = make_float4(v[4], v[5], v[6], v[7]);
        float* Pr = &d_P[((size_t)b * NL + r) * NL + ct + tx * 8];
        *reinterpret_cast<float4*>(Pr)     = s0;
        *reinterpret_cast<float4*>(Pr + 4) = s1;
        float rm = fmaxf(fmaxf(fmaxf(v[0], v[1]), fmaxf(v[2], v[3])),
                         fmaxf(fmaxf(v[4], v[5]), fmaxf(v[6], v[7])));
        // butterfly over the 16 tx lanes (stays within half-warp)
#pragma unroll
        for (int off = 8; off > 0; off >>= 1)
            rm = fmaxf(rm, __shfl_xor_sync(0xFFFFFFFFu, rm, off));
        if (tx == 0) atomicMax(&rowm[ty * 8 + i], fenc(rm));
    }
    __syncthreads();
    if (tid < 128) atomicMax(&men[b * NL + rt + tid], rowm[tid]);
}

// ---------------- sparse build: warp per row, deterministic ordered compaction ----------------
__global__ __launch_bounds__(256) void sparse_build_kernel()
{
    int gtid = blockIdx.x * blockDim.x + threadIdx.x;
    int w    = gtid >> 5;       // row index (b*NL + l)
    int lane = gtid & 31;
    if (w >= NB * NL) return;
    const float* Pr = d_P + (size_t)w * NL;
    float m = fdec(d_mA[w]);
    float thr = m - STHRESH;
    int base = 0;
    size_t sb = (size_t)w * SCAP;
    for (int k0 = 0; k0 < NL; k0 += 32) {
        float p = Pr[k0 + lane];
        bool keep = (p > thr);
        unsigned mask = __ballot_sync(0xFFFFFFFFu, keep);
        if (keep) {
            int pos = base + __popc(mask & ((1u << lane) - 1u));
            if (pos < SCAP)
                d_sv2[sb + pos] = make_float2(__int_as_float(k0 + lane), __expf(p - m));
        }
        base += __popc(mask);
    }
    if (lane == 0) {
        int cnt = (base < SCAP) ? base : SCAP;
        int padded = (cnt + 3) & ~3;
        if (padded > SCAP) padded = SCAP;
        for (int p = cnt; p < padded; p++)
            d_sv2[sb + p] = make_float2(__int_as_float(0), 0.f);
        d_scnt[w] = padded;
    }
}

// ---------------- 100 iterations in one launch: one block per batch ----------------
__global__ __launch_bounds__(1024) void iterate_kernel(const float* __restrict__ lw)
{
    const int b   = blockIdx.x;
    const int tid = threadIdx.x;        // 1024 threads, 2 rows each
    __shared__ float us[NL];

    const int r0 = tid, r1 = tid + 1024;
    const float m0 = fdec(d_mA[b * NL + r0]);
    const float m1 = fdec(d_mA[b * NL + r1]);
    const int   n0 = d_scnt[b * NL + r0];
    const int   n1 = d_scnt[b * NL + r1];
    const float2* lp0 = d_sv2 + ((size_t)b * NL + r0) * SCAP;
    const float2* lp1 = d_sv2 + ((size_t)b * NL + r1) * SCAP;

    float f0 = 0.f, f1 = 0.f;

    for (int it = 0; it < NITER; it++) {
        us[r0] = __expf(f0);
        us[r1] = __expf(f1);
        __syncthreads();
        float s0 = 0.f;
        for (int j = 0; j < n0; j += 4) {
            float2 e0 = lp0[j], e1 = lp0[j + 1], e2 = lp0[j + 2], e3 = lp0[j + 3];
            s0 += e0.y * us[__float_as_int(e0.x)];
            s0 += e1.y * us[__float_as_int(e1.x)];
            s0 += e2.y * us[__float_as_int(e2.x)];
            s0 += e3.y * us[__float_as_int(e3.x)];
        }
        float s1 = 0.f;
        for (int j = 0; j < n1; j += 4) {
            float2 e0 = lp1[j], e1 = lp1[j + 1], e2 = lp1[j + 2], e3 = lp1[j + 3];
            s1 += e0.y * us[__float_as_int(e0.x)];
            s1 += e1.y * us[__float_as_int(e1.x)];
            s1 += e2.y * us[__float_as_int(e2.x)];
            s1 += e3.y * us[__float_as_int(e3.x)];
        }
        float fn0 = 0.5f * (f0 - m0 - __logf(s0));
        float fn1 = 0.5f * (f1 - m1 - __logf(s1));
        __syncthreads();   // all u-reads done before anyone overwrites us
        f0 = fn0;
        f1 = fn1;
    }
    // column bias for the cross pass: lw_l + f_l - 0.5*||pos_l||^2
    d_cbC[b * NL + r0] = lw[b * NL + r0] + f0 + d_rbA[b * NL + r0];
    d_cbC[b * NL + r1] = lw[b * NL + r1] + f1 + d_rbA[b * NL + r1];
}

// ---------------- cross LSE: block per target row (max precomputed by score<1>) ----------------
__global__ __launch_bounds__(256) void lse_cross_kernel(const float* __restrict__ tlw)
{
    const int row = blockIdx.x;              // b*NL + t
    const float4* Sr4 = reinterpret_cast<const float4*>(d_P + (size_t)row * NL);
    float m = fdec(d_mC[row]);
    float s = 0.f;
    for (int k = threadIdx.x; k < NL / 4; k += 256) {
        float4 v = Sr4[k];
        s += __expf(v.x - m) + __expf(v.y - m) + __expf(v.z - m) + __expf(v.w - m);
    }
    __shared__ float red[256];
    red[threadIdx.x] = s;
    __syncthreads();
    for (int off = 128; off > 0; off >>= 1) {
        if (threadIdx.x < off) red[threadIdx.x] += red[threadIdx.x + off];
        __syncthreads();
    }
    if (threadIdx.x == 0) {
        float g = -(m + __logf(red[0]));
        d_gw[row] = g * __expf(tlw[row]);
    }
}

// ---------------- deterministic final reduction ----------------
__global__ __launch_bounds__(256) void reduce_kernel(float* __restrict__ out)
{
    const int b = blockIdx.x;
    float s = 0.f;
    for (int k = threadIdx.x; k < NL; k += 256) s += d_gw[b * NL + k];
    __shared__ float red[256];
    red[threadIdx.x] = s;
    __syncthreads();
    for (int off = 128; off > 0; off >>= 1) {
        if (threadIdx.x < off) red[threadIdx.x] += red[threadIdx.x + off];
        __syncthreads();
    }
    if (threadIdx.x == 0) out[b] = red[0];
}

// ---------------- launch ----------------
extern "C" void kernel_launch(void* const* d_in, const int* in_sizes, int n_in,
                              void* d_out, int out_size)
{
    const float* pos  = (const float*)d_in[0];   // (8, 2048, 64)
    const float* lw   = (const float*)d_in[1];   // (8, 2048)
    const float* tpos = (const float*)d_in[2];   // (8, 2048, 64)
    const float* tlw  = (const float*)d_in[3];   // (8, 2048)
    float* out = (float*)d_out;                  // (8,)

    prep_kernel<<<(NB * NL + 255) / 256, 256>>>(pos, lw, tpos);

    dim3 g(NL / 128, NL / 128, NB);
    score_kernel<0><<<g, 256>>>(pos, pos);

    sparse_build_kernel<<<(NB * NL * 32) / 256, 256>>>();

    iterate_kernel<<<NB, 1024>>>(lw);

    score_kernel<1><<<g, 256>>>(tpos, pos);

    lse_cross_kernel<<<NB * NL, 256>>>(tlw);

    reduce_kernel<<<NB, 256>>>(out);
}